// round 12
// baseline (speedup 1.0000x reference)
#include <cuda_runtime.h>
#include <cuda_fp16.h>

// SoftPerspectiveShader: barycentric texture sampling + softmax RGB blend.
// N=4,H=W=512,K=8,F=200000.
//
// R10: shader is at the chip LTS/DRAM cap (79% DRAM, 6.25TB/s) -> only byte
// reduction helps. (a) repack vectorized: float4 staging (576 LDG.128/block
// instead of 2304 LDG.32). (b) bary: load b0,b1 only, b2 = 1-b0-b1
// (normalized by construction) -> 8B/survivor, fewer sector crossings.

#define P3D_SIGMA   1e-4f
#define P3D_GAMMA   1e-4f
#define P3D_ZNEAR   1.0f
#define P3D_ZFAR    100.0f
#define P3D_EPS     1e-10f
#define E_CUT       (-3.0e-3f)   // exp(E_CUT/gamma) = exp(-30) ~ 9e-14

#define F_MAX 200000

// fp16 color table: 16 halves (32B) per face, first 9 used. 6.4 MB scratch.
__device__ __align__(16) __half2 g_fcol_h[F_MAX * 8];

// Repack: 256 faces/block, float4-staged coalesced reads -> 32B fp16/face.
__global__ void __launch_bounds__(256)
repack_kernel(const float4* __restrict__ fcol4, const float* __restrict__ fcol,
              int F)
{
    __shared__ float s[256 * 9];
    int base  = blockIdx.x * 256;             // first face of this block
    int nf    = min(256, F - base);
    int nflt  = nf * 9;
    int base_flt = base * 9;

    if (nf == 256) {
        // full block: 2304 floats = 576 float4, vectorized staging
        const float4* src = fcol4 + (base_flt >> 2);   // base_flt % 4 may be != 0? base*9*4B: base mult of 256 -> base_flt mult of 2304 -> /4 ok (2304%4==0)
        float4* s4 = (float4*)s;
        #pragma unroll
        for (int i = 0; i < 3; i++) {
            int idx = threadIdx.x + i * 256;
            if (idx < 576) s4[idx] = __ldg(src + idx);
        }
    } else {
        for (int i = threadIdx.x; i < nflt; i += 256)
            s[i] = fcol[base_flt + i];
    }
    __syncthreads();

    int t = threadIdx.x;
    if (t >= nf) return;
    const float* v = s + t * 9;               // stride 9: bank-conflict-free
    __half2 h0 = __floats2half2_rn(v[0], v[1]);
    __half2 h1 = __floats2half2_rn(v[2], v[3]);
    __half2 h2 = __floats2half2_rn(v[4], v[5]);
    __half2 h3 = __floats2half2_rn(v[6], v[7]);
    __half2 h4 = __floats2half2_rn(v[8], 0.f);
    uint4 a, b;
    a.x = *(unsigned*)&h0; a.y = *(unsigned*)&h1;
    a.z = *(unsigned*)&h2; a.w = *(unsigned*)&h3;
    b.x = *(unsigned*)&h4; b.y = 0u; b.z = 0u; b.w = 0u;
    uint4* dst = (uint4*)(g_fcol_h + (size_t)(base + t) * 8);
    dst[0] = a;
    dst[1] = b;
}

__global__ void __launch_bounds__(256)
soft_shader_kernel(const int4*   __restrict__ p2f4,
                   const float4* __restrict__ zbuf4,
                   const float4* __restrict__ dist4,
                   const float*  __restrict__ bary,
                   float4*       __restrict__ out,
                   int npix)
{
    int pix = blockIdx.x * blockDim.x + threadIdx.x;
    if (pix >= npix) return;

    // -------- vectorized streaming loads: 6x LDG.128, all independent ------
    int4   pA = __ldg(p2f4  + 2 * pix);
    int4   pB = __ldg(p2f4  + 2 * pix + 1);
    float4 zA = __ldg(zbuf4 + 2 * pix);
    float4 zB = __ldg(zbuf4 + 2 * pix + 1);
    float4 dA = __ldg(dist4 + 2 * pix);
    float4 dB = __ldg(dist4 + 2 * pix + 1);

    int   pf[8] = { pA.x, pA.y, pA.z, pA.w, pB.x, pB.y, pB.z, pB.w };
    float zz[8] = { zA.x, zA.y, zA.z, zA.w, zB.x, zB.y, zB.z, zB.w };
    float dd[8] = { dA.x, dA.y, dA.z, dA.w, dB.x, dB.y, dB.z, dB.w };

    // -------- pass 1: prob, zinv, zmax, alpha-product --------
    float prob[8], zinv[8];
    float zmax = P3D_EPS;
    float om   = 1.0f;
    #pragma unroll
    for (int k = 0; k < 8; k++) {
        bool m  = (pf[k] >= 0);
        prob[k] = m ? (1.0f / (1.0f + __expf(dd[k] * (1.0f / P3D_SIGMA)))) : 0.0f;
        zinv[k] = m ? (P3D_ZFAR - zz[k]) * (1.0f / (P3D_ZFAR - P3D_ZNEAR)) : 0.0f;
        zmax    = fmaxf(zmax, zinv[k]);
        om     *= (1.0f - prob[k]);
    }

    // -------- pass 2: weights + predicated gather (~1 of 8 survives) -------
    float sw = 0.f, sr = 0.f, sg = 0.f, sb = 0.f;
    #pragma unroll
    for (int k = 0; k < 8; k++) {
        float e = zinv[k] - zmax;                 // <= 0
        if (e > E_CUT && pf[k] >= 0) {
            float w = prob[k] * __expf(e * (1.0f / P3D_GAMMA));
            const float* bp = bary + 24 * pix + 3 * k;
            float b0 = __ldg(bp + 0);
            float b1 = __ldg(bp + 1);
            float b2 = 1.0f - b0 - b1;            // bary normalized along K,3
            const uint4* gp = (const uint4*)(g_fcol_h + (size_t)pf[k] * 8);
            uint4    a  = __ldg(gp);
            unsigned b4 = __ldg((const unsigned*)(gp + 1));
            float2 q0 = __half22float2(*(__half2*)&a.x);   // c00 c01
            float2 q1 = __half22float2(*(__half2*)&a.y);   // c02 c10
            float2 q2 = __half22float2(*(__half2*)&a.z);   // c11 c12
            float2 q3 = __half22float2(*(__half2*)&a.w);   // c20 c21
            float  c22 = __low2float(*(__half2*)&b4);
            float tr = b0 * q0.x + b1 * q1.y + b2 * q3.x;
            float tg = b0 * q0.y + b1 * q2.x + b2 * q3.y;
            float tb = b0 * q1.x + b1 * q2.y + b2 * c22;
            sw += w;
            sr += w * tr;
            sg += w * tg;
            sb += w * tb;
        }
    }

    // -------- epilogue: once per pixel --------
    float delta = fmaxf(__expf((P3D_EPS - zmax) * (1.0f / P3D_GAMMA)), P3D_EPS);
    float inv   = 1.0f / (sw + delta);
    // background = (1,1,1):  rgb_c = (sum_c + delta) / denom
    out[pix] = make_float4((sr + delta) * inv,
                           (sg + delta) * inv,
                           (sb + delta) * inv,
                           om);
}

extern "C" void kernel_launch(void* const* d_in, const int* in_sizes, int n_in,
                              void* d_out, int out_size)
{
    const int*   p2f   = (const int*)  d_in[0];   // pix_to_face [N,H,W,K]
    const float* bary  = (const float*)d_in[1];   // bary_coords [N,H,W,K,3]
    const float* zbuf  = (const float*)d_in[2];   // zbuf        [N,H,W,K]
    const float* dists = (const float*)d_in[3];   // dists       [N,H,W,K]
    const float* fcol  = (const float*)d_in[4];   // face_colors [F,3,3]
    float4* out = (float4*)d_out;                 // [N,H,W,4]

    int F = in_sizes[4] / 9;
    if (F > F_MAX) F = F_MAX;
    repack_kernel<<<(F + 255) / 256, 256>>>((const float4*)fcol, fcol, F);

    int npix = in_sizes[0] / 8;                   // N*H*W = 1048576
    int threads = 256;
    int blocks  = (npix + threads - 1) / threads;
    soft_shader_kernel<<<blocks, threads>>>((const int4*)p2f,
                                            (const float4*)zbuf,
                                            (const float4*)dists,
                                            bary, out, npix);
}

// round 16
// speedup vs baseline: 1.0054x; 1.0054x over previous
#include <cuda_runtime.h>

// SoftPerspectiveShader: barycentric texture sampling + softmax RGB blend.
// N=4,H=W=512,K=8,F=200000.
//
// R12: delete the repack pass. R10's neutral result showed the ~6us gap is
// the second launch + its 13.6MB DRAM traffic, not the repack inner loop.
// With the predicated gather only ~1.05 fragments/pixel read colors, so we
// gather directly from the fp32 face_colors table (9 scalar LDGs on ~4
// lanes/warp; L1=38%, L2=49% had headroom). Single kernel, fp32 accuracy.

#define P3D_SIGMA   1e-4f
#define P3D_GAMMA   1e-4f
#define P3D_ZNEAR   1.0f
#define P3D_ZFAR    100.0f
#define P3D_EPS     1e-10f
#define E_CUT       (-3.0e-3f)   // exp(E_CUT/gamma) = exp(-30) ~ 9e-14

__global__ void __launch_bounds__(256)
soft_shader_kernel(const int4*   __restrict__ p2f4,
                   const float4* __restrict__ zbuf4,
                   const float4* __restrict__ dist4,
                   const float*  __restrict__ bary,
                   const float*  __restrict__ fcol,
                   float4*       __restrict__ out,
                   int npix)
{
    int pix = blockIdx.x * blockDim.x + threadIdx.x;
    if (pix >= npix) return;

    // -------- vectorized streaming loads: 6x LDG.128, all independent ------
    int4   pA = __ldg(p2f4  + 2 * pix);
    int4   pB = __ldg(p2f4  + 2 * pix + 1);
    float4 zA = __ldg(zbuf4 + 2 * pix);
    float4 zB = __ldg(zbuf4 + 2 * pix + 1);
    float4 dA = __ldg(dist4 + 2 * pix);
    float4 dB = __ldg(dist4 + 2 * pix + 1);

    int   pf[8] = { pA.x, pA.y, pA.z, pA.w, pB.x, pB.y, pB.z, pB.w };
    float zz[8] = { zA.x, zA.y, zA.z, zA.w, zB.x, zB.y, zB.z, zB.w };
    float dd[8] = { dA.x, dA.y, dA.z, dA.w, dB.x, dB.y, dB.z, dB.w };

    // -------- pass 1: prob, zinv, zmax, alpha-product --------
    float prob[8], zinv[8];
    float zmax = P3D_EPS;
    float om   = 1.0f;
    #pragma unroll
    for (int k = 0; k < 8; k++) {
        bool m  = (pf[k] >= 0);
        prob[k] = m ? (1.0f / (1.0f + __expf(dd[k] * (1.0f / P3D_SIGMA)))) : 0.0f;
        zinv[k] = m ? (P3D_ZFAR - zz[k]) * (1.0f / (P3D_ZFAR - P3D_ZNEAR)) : 0.0f;
        zmax    = fmaxf(zmax, zinv[k]);
        om     *= (1.0f - prob[k]);
    }

    // -------- pass 2: weights + predicated gather (~1 of 8 survives) -------
    float sw = 0.f, sr = 0.f, sg = 0.f, sb = 0.f;
    #pragma unroll
    for (int k = 0; k < 8; k++) {
        float e = zinv[k] - zmax;                 // <= 0
        if (e > E_CUT && pf[k] >= 0) {
            float w = prob[k] * __expf(e * (1.0f / P3D_GAMMA));
            const float* bp = bary + 24 * pix + 3 * k;
            float b0 = __ldg(bp + 0);
            float b1 = __ldg(bp + 1);
            float b2 = 1.0f - b0 - b1;            // bary normalized along K,3

            const float* c = fcol + (size_t)pf[k] * 9;
            float c00 = __ldg(c + 0), c01 = __ldg(c + 1), c02 = __ldg(c + 2);
            float c10 = __ldg(c + 3), c11 = __ldg(c + 4), c12 = __ldg(c + 5);
            float c20 = __ldg(c + 6), c21 = __ldg(c + 7), c22 = __ldg(c + 8);

            float tr = b0 * c00 + b1 * c10 + b2 * c20;
            float tg = b0 * c01 + b1 * c11 + b2 * c21;
            float tb = b0 * c02 + b1 * c12 + b2 * c22;
            sw += w;
            sr += w * tr;
            sg += w * tg;
            sb += w * tb;
        }
    }

    // -------- epilogue: once per pixel --------
    float delta = fmaxf(__expf((P3D_EPS - zmax) * (1.0f / P3D_GAMMA)), P3D_EPS);
    float inv   = 1.0f / (sw + delta);
    // background = (1,1,1):  rgb_c = (sum_c + delta) / denom
    out[pix] = make_float4((sr + delta) * inv,
                           (sg + delta) * inv,
                           (sb + delta) * inv,
                           om);
}

extern "C" void kernel_launch(void* const* d_in, const int* in_sizes, int n_in,
                              void* d_out, int out_size)
{
    const int*   p2f   = (const int*)  d_in[0];   // pix_to_face [N,H,W,K]
    const float* bary  = (const float*)d_in[1];   // bary_coords [N,H,W,K,3]
    const float* zbuf  = (const float*)d_in[2];   // zbuf        [N,H,W,K]
    const float* dists = (const float*)d_in[3];   // dists       [N,H,W,K]
    const float* fcol  = (const float*)d_in[4];   // face_colors [F,3,3]
    float4* out = (float4*)d_out;                 // [N,H,W,4]

    int npix = in_sizes[0] / 8;                   // N*H*W = 1048576
    int threads = 256;
    int blocks  = (npix + threads - 1) / threads;
    soft_shader_kernel<<<blocks, threads>>>((const int4*)p2f,
                                            (const float4*)zbuf,
                                            (const float4*)dists,
                                            bary, fcol, out, npix);
}